// round 1
// baseline (speedup 1.0000x reference)
#include <cuda_runtime.h>
#include <math.h>

#define NN 10000
#define EE 160000
#define FIN 70
#define HIDC 256
#define NHEADS 4
#define D1 1024   // NHEADS*HIDC

// ---------------- scratch (device globals; no allocations) ----------------
__device__ float g_h1[(size_t)NN * D1];     // layer1 pre-attention features
__device__ float g_x1[(size_t)NN * D1];     // layer1 output (relu)
__device__ float g_h2[(size_t)NN * HIDC];   // layer2 pre-attention features
__device__ float g_x2[(size_t)NN * HIDC];   // layer2 output (relu)
__device__ float g_as1[NN * NHEADS];
__device__ float g_ad1[NN * NHEADS];
__device__ float g_as2[NN];
__device__ float g_ad2[NN];
__device__ int   g_cnt[NN];
__device__ int   g_rowptr[NN + 1];
__device__ int   g_fill[NN];
__device__ int   g_csrsrc[EE];
__device__ float g_pooled[HIDC];

// ---------------- CSR build ----------------
__global__ void k_zero() {
    int i = blockIdx.x * blockDim.x + threadIdx.x;
    if (i < NN) g_cnt[i] = 0;
    if (i < HIDC) g_pooled[i] = 0.f;
}

__global__ void k_hist(const int* __restrict__ ei) {
    int e = blockIdx.x * blockDim.x + threadIdx.x;
    if (e < EE) atomicAdd(&g_cnt[ei[EE + e]], 1);
}

__global__ void k_scan() {
    __shared__ int tile[1024];
    __shared__ int carry;
    int t = threadIdx.x;
    if (t == 0) carry = 0;
    __syncthreads();
    for (int base = 0; base < NN; base += 1024) {
        int i = base + t;
        int v = (i < NN) ? g_cnt[i] : 0;
        tile[t] = v;
        __syncthreads();
        for (int off = 1; off < 1024; off <<= 1) {
            int tmp = (t >= off) ? tile[t - off] : 0;
            __syncthreads();
            tile[t] += tmp;
            __syncthreads();
        }
        int incl = tile[t];
        int c = carry;
        if (i < NN) { g_rowptr[i] = c + incl - v; g_fill[i] = c + incl - v; }
        __syncthreads();
        if (t == 1023) carry = c + tile[1023];
        __syncthreads();
    }
    if (t == 0) g_rowptr[NN] = carry;
}

__global__ void k_fill(const int* __restrict__ ei) {
    int e = blockIdx.x * blockDim.x + threadIdx.x;
    if (e < EE) {
        int d = ei[EE + e];
        int p = atomicAdd(&g_fill[d], 1);
        g_csrsrc[p] = ei[e];
    }
}

// ---------------- GEMM1: X[N,70] @ W1[70,1024] -> g_h1 ----------------
__global__ void __launch_bounds__(256) k_gemm1(const float* __restrict__ X,
                                               const float* __restrict__ W1) {
    __shared__ float As[64][FIN + 2];   // [row][k]
    __shared__ float Bs[FIN][64];       // [k][col]
    int m0 = blockIdx.y * 64, n0 = blockIdx.x * 64;
    int t = threadIdx.x;
    for (int idx = t; idx < 64 * FIN; idx += 256) {
        int r = idx / FIN, c = idx - r * FIN;
        int gr = m0 + r;
        As[r][c] = (gr < NN) ? X[(size_t)gr * FIN + c] : 0.f;
    }
    for (int idx = t; idx < FIN * 64; idx += 256) {
        int k = idx >> 6, c = idx & 63;
        Bs[k][c] = W1[(size_t)k * D1 + n0 + c];
    }
    __syncthreads();
    int ty = t >> 4, tx = t & 15;
    int rm = ty * 4, rn = tx * 4;
    float acc[4][4] = {};
#pragma unroll 2
    for (int k = 0; k < FIN; k++) {
        float a0 = As[rm][k], a1 = As[rm + 1][k], a2 = As[rm + 2][k], a3 = As[rm + 3][k];
        float4 b4 = *(const float4*)&Bs[k][rn];
        acc[0][0] += a0 * b4.x; acc[0][1] += a0 * b4.y; acc[0][2] += a0 * b4.z; acc[0][3] += a0 * b4.w;
        acc[1][0] += a1 * b4.x; acc[1][1] += a1 * b4.y; acc[1][2] += a1 * b4.z; acc[1][3] += a1 * b4.w;
        acc[2][0] += a2 * b4.x; acc[2][1] += a2 * b4.y; acc[2][2] += a2 * b4.z; acc[2][3] += a2 * b4.w;
        acc[3][0] += a3 * b4.x; acc[3][1] += a3 * b4.y; acc[3][2] += a3 * b4.z; acc[3][3] += a3 * b4.w;
    }
#pragma unroll
    for (int i = 0; i < 4; i++) {
        int gr = m0 + rm + i;
        if (gr < NN) {
            float4 v = make_float4(acc[i][0], acc[i][1], acc[i][2], acc[i][3]);
            *(float4*)&g_h1[(size_t)gr * D1 + n0 + rn] = v;
        }
    }
}

// ---------------- GEMM2: x1[N,1024] @ W2[1024,256] -> g_h2 ----------------
__global__ void __launch_bounds__(256) k_gemm2(const float* __restrict__ W2) {
    __shared__ float As[16][128 + 4];   // [k][m]
    __shared__ float Bs[16][128];       // [k][n]
    int m0 = blockIdx.y * 128, n0 = blockIdx.x * 128;
    int t = threadIdx.x;
    int ty = t >> 4, tx = t & 15;
    int tm0 = ty * 8, tn0 = tx * 8;
    float acc[8][8] = {};
    for (int kb = 0; kb < D1; kb += 16) {
#pragma unroll
        for (int r = 0; r < 8; r++) {
            int i = t + 256 * r;
            int row = i >> 4, kk = i & 15;
            int gr = m0 + row;
            float v = 0.f;
            if (gr < NN) v = g_x1[(size_t)gr * D1 + kb + kk];
            As[kk][row] = v;
        }
#pragma unroll
        for (int r = 0; r < 8; r++) {
            int i = t + 256 * r;
            int kk = i >> 7, col = i & 127;
            Bs[kk][col] = W2[(size_t)(kb + kk) * HIDC + n0 + col];
        }
        __syncthreads();
#pragma unroll
        for (int k = 0; k < 16; k++) {
            float4 a0 = *(const float4*)&As[k][tm0];
            float4 a1 = *(const float4*)&As[k][tm0 + 4];
            float4 b0 = *(const float4*)&Bs[k][tn0];
            float4 b1 = *(const float4*)&Bs[k][tn0 + 4];
            float a[8] = {a0.x, a0.y, a0.z, a0.w, a1.x, a1.y, a1.z, a1.w};
            float b[8] = {b0.x, b0.y, b0.z, b0.w, b1.x, b1.y, b1.z, b1.w};
#pragma unroll
            for (int i = 0; i < 8; i++)
#pragma unroll
                for (int j = 0; j < 8; j++)
                    acc[i][j] += a[i] * b[j];
        }
        __syncthreads();
    }
#pragma unroll
    for (int i = 0; i < 8; i++) {
        int gr = m0 + tm0 + i;
        if (gr < NN) {
            float4 v0 = make_float4(acc[i][0], acc[i][1], acc[i][2], acc[i][3]);
            float4 v1 = make_float4(acc[i][4], acc[i][5], acc[i][6], acc[i][7]);
            *(float4*)&g_h2[(size_t)gr * HIDC + n0 + tn0] = v0;
            *(float4*)&g_h2[(size_t)gr * HIDC + n0 + tn0 + 4] = v1;
        }
    }
}

// ---------------- attention dot products ----------------
__global__ void k_dots1(const float* __restrict__ att_s, const float* __restrict__ att_d) {
    int i = blockIdx.x;
    int w = threadIdx.x >> 5, lane = threadIdx.x & 31;
    const float* hrow = g_h1 + (size_t)i * D1 + w * HIDC;
    const float* avs = att_s + w * HIDC;
    const float* avd = att_d + w * HIDC;
    float s = 0.f, d = 0.f;
    for (int c = lane; c < HIDC; c += 32) {
        float v = hrow[c];
        s += v * avs[c];
        d += v * avd[c];
    }
    for (int o = 16; o; o >>= 1) {
        s += __shfl_xor_sync(0xffffffffu, s, o);
        d += __shfl_xor_sync(0xffffffffu, d, o);
    }
    if (lane == 0) { g_as1[i * NHEADS + w] = s; g_ad1[i * NHEADS + w] = d; }
}

__global__ void k_dots2(const float* __restrict__ att_s, const float* __restrict__ att_d) {
    int w = threadIdx.x >> 5, lane = threadIdx.x & 31;
    int i = blockIdx.x * 8 + w;
    if (i >= NN) return;
    const float* hrow = g_h2 + (size_t)i * HIDC;
    float s = 0.f, d = 0.f;
    for (int c = lane; c < HIDC; c += 32) {
        float v = hrow[c];
        s += v * att_s[c];
        d += v * att_d[c];
    }
    for (int o = 16; o; o >>= 1) {
        s += __shfl_xor_sync(0xffffffffu, s, o);
        d += __shfl_xor_sync(0xffffffffu, d, o);
    }
    if (lane == 0) { g_as2[i] = s; g_ad2[i] = d; }
}

// ---------------- fused softmax + aggregation, layer 1 ----------------
__global__ void __launch_bounds__(256) k_agg1(const float* __restrict__ b1) {
    int dd = blockIdx.x, t = threadIdx.x;
    int beg = g_rowptr[dd], deg = g_rowptr[dd + 1] - beg, total = deg + 1;
    const float4* as4 = (const float4*)g_as1;
    float4 adv4 = ((const float4*)g_ad1)[dd];
    float ad[4] = {adv4.x, adv4.y, adv4.z, adv4.w};

    // pass 1: per-head max over in-edges (+ implicit self-loop)
    float mx[4] = {-1e30f, -1e30f, -1e30f, -1e30f};
    for (int j = t; j < total; j += 256) {
        int s = (j < deg) ? g_csrsrc[beg + j] : dd;
        float4 a4 = as4[s];
        float e;
        e = a4.x + ad[0]; e = e > 0.f ? e : 0.2f * e; mx[0] = fmaxf(mx[0], e);
        e = a4.y + ad[1]; e = e > 0.f ? e : 0.2f * e; mx[1] = fmaxf(mx[1], e);
        e = a4.z + ad[2]; e = e > 0.f ? e : 0.2f * e; mx[2] = fmaxf(mx[2], e);
        e = a4.w + ad[3]; e = e > 0.f ? e : 0.2f * e; mx[3] = fmaxf(mx[3], e);
    }
    __shared__ float sred[8][4];
    int lane = t & 31, w = t >> 5;
#pragma unroll
    for (int h = 0; h < 4; h++)
        for (int o = 16; o; o >>= 1) mx[h] = fmaxf(mx[h], __shfl_xor_sync(0xffffffffu, mx[h], o));
    if (lane == 0) { sred[w][0] = mx[0]; sred[w][1] = mx[1]; sred[w][2] = mx[2]; sred[w][3] = mx[3]; }
    __syncthreads();
    __shared__ float m_s[4];
    if (t < 4) {
        float m = sred[0][t];
        for (int i = 1; i < 8; i++) m = fmaxf(m, sred[i][t]);
        m_s[t] = m;
    }
    __syncthreads();
    float m[4] = {m_s[0], m_s[1], m_s[2], m_s[3]};

    // pass 2: unnormalized weights + gather/accumulate
    __shared__ float4 sw[256];
    __shared__ int ssrc[256];
    float acc[4] = {0.f, 0.f, 0.f, 0.f};
    float dl[4] = {0.f, 0.f, 0.f, 0.f};
    for (int base = 0; base < total; base += 256) {
        int j = base + t;
        int cn = min(256, total - base);
        if (j < total) {
            int s = (j < deg) ? g_csrsrc[beg + j] : dd;
            float4 a4 = as4[s];
            float e, w0, w1, w2, w3;
            e = a4.x + ad[0]; e = e > 0.f ? e : 0.2f * e; w0 = __expf(e - m[0]); dl[0] += w0;
            e = a4.y + ad[1]; e = e > 0.f ? e : 0.2f * e; w1 = __expf(e - m[1]); dl[1] += w1;
            e = a4.z + ad[2]; e = e > 0.f ? e : 0.2f * e; w2 = __expf(e - m[2]); dl[2] += w2;
            e = a4.w + ad[3]; e = e > 0.f ? e : 0.2f * e; w3 = __expf(e - m[3]); dl[3] += w3;
            sw[t] = make_float4(w0, w1, w2, w3);
            ssrc[t] = s;
        }
        __syncthreads();
#pragma unroll 2
        for (int j2 = 0; j2 < cn; j2++) {
            int s = ssrc[j2];
            float4 wv = sw[j2];
            const float* hp = g_h1 + (size_t)s * D1 + t;
            acc[0] += wv.x * hp[0];
            acc[1] += wv.y * hp[256];
            acc[2] += wv.z * hp[512];
            acc[3] += wv.w * hp[768];
        }
        __syncthreads();
    }
#pragma unroll
    for (int h = 0; h < 4; h++)
        for (int o = 16; o; o >>= 1) dl[h] += __shfl_xor_sync(0xffffffffu, dl[h], o);
    if (lane == 0) { sred[w][0] = dl[0]; sred[w][1] = dl[1]; sred[w][2] = dl[2]; sred[w][3] = dl[3]; }
    __syncthreads();
    __shared__ float den_s[4];
    if (t < 4) {
        float s = 0.f;
        for (int i = 0; i < 8; i++) s += sred[i][t];
        den_s[t] = s;
    }
    __syncthreads();
#pragma unroll
    for (int h = 0; h < 4; h++) {
        float o = acc[h] / (den_s[h] + 1e-16f) + b1[h * HIDC + t];
        g_x1[(size_t)dd * D1 + h * HIDC + t] = o > 0.f ? o : 0.f;
    }
}

// ---------------- fused softmax + aggregation, layer 2 (1 head) ----------------
__global__ void __launch_bounds__(256) k_agg2(const float* __restrict__ b2) {
    int dd = blockIdx.x, t = threadIdx.x;
    int beg = g_rowptr[dd], deg = g_rowptr[dd + 1] - beg, total = deg + 1;
    float adv = g_ad2[dd];
    float mx = -1e30f;
    for (int j = t; j < total; j += 256) {
        int s = (j < deg) ? g_csrsrc[beg + j] : dd;
        float e = g_as2[s] + adv; e = e > 0.f ? e : 0.2f * e;
        mx = fmaxf(mx, e);
    }
    __shared__ float sred[8];
    int lane = t & 31, w = t >> 5;
    for (int o = 16; o; o >>= 1) mx = fmaxf(mx, __shfl_xor_sync(0xffffffffu, mx, o));
    if (lane == 0) sred[w] = mx;
    __syncthreads();
    __shared__ float m_s;
    if (t == 0) {
        float m = sred[0];
        for (int i = 1; i < 8; i++) m = fmaxf(m, sred[i]);
        m_s = m;
    }
    __syncthreads();
    float m = m_s;

    __shared__ float sw[256];
    __shared__ int ssrc[256];
    float acc = 0.f, dl = 0.f;
    for (int base = 0; base < total; base += 256) {
        int j = base + t;
        int cn = min(256, total - base);
        if (j < total) {
            int s = (j < deg) ? g_csrsrc[beg + j] : dd;
            float e = g_as2[s] + adv; e = e > 0.f ? e : 0.2f * e;
            float wv = __expf(e - m);
            sw[t] = wv; ssrc[t] = s; dl += wv;
        }
        __syncthreads();
#pragma unroll 4
        for (int j2 = 0; j2 < cn; j2++) {
            acc += sw[j2] * g_h2[(size_t)ssrc[j2] * HIDC + t];
        }
        __syncthreads();
    }
    for (int o = 16; o; o >>= 1) dl += __shfl_xor_sync(0xffffffffu, dl, o);
    if (lane == 0) sred[w] = dl;
    __syncthreads();
    __shared__ float den_s;
    if (t == 0) {
        float s = 0.f;
        for (int i = 0; i < 8; i++) s += sred[i];
        den_s = s;
    }
    __syncthreads();
    float o = acc / (den_s + 1e-16f) + b2[t];
    g_x2[(size_t)dd * HIDC + t] = o > 0.f ? o : 0.f;
}

// ---------------- pooling + MLP head ----------------
__global__ void k_pool() {
    int c = threadIdx.x;
    float s = 0.f;
    for (int i = blockIdx.x; i < NN; i += gridDim.x) s += g_x2[(size_t)i * HIDC + c];
    atomicAdd(&g_pooled[c], s);
}

__global__ void k_final(const float* __restrict__ Wv1, const float* __restrict__ bv1,
                        const float* __restrict__ Wv2, const float* __restrict__ bv2,
                        float* __restrict__ out) {
    __shared__ float red[128];
    int j = threadIdx.x;  // 128
    float acc = bv1[j];
    const float inv_n = 1.0f / (float)NN;
    for (int c = 0; c < HIDC; c++)
        acc += (g_pooled[c] * inv_n) * Wv1[c * 128 + j];
    float x = acc;
    float g = 0.5f * x * (1.0f + erff(x * 0.70710678118654752f));
    red[j] = g * Wv2[j];
    __syncthreads();
    for (int o = 64; o; o >>= 1) {
        if (j < o) red[j] += red[j + o];
        __syncthreads();
    }
    if (j == 0) out[0] = red[0] + bv2[0];
}

// ---------------- launch ----------------
extern "C" void kernel_launch(void* const* d_in, const int* in_sizes, int n_in,
                              void* d_out, int out_size) {
    const float* X   = (const float*)d_in[0];
    const int*   ei  = (const int*)d_in[1];
    // d_in[2] = edge_attr (ignored: GATConv has no edge_dim)
    const float* W1  = (const float*)d_in[3];
    const float* as1 = (const float*)d_in[4];
    const float* ad1 = (const float*)d_in[5];
    const float* b1  = (const float*)d_in[6];
    const float* W2  = (const float*)d_in[7];
    const float* as2 = (const float*)d_in[8];
    const float* ad2 = (const float*)d_in[9];
    const float* b2  = (const float*)d_in[10];
    const float* Wv1 = (const float*)d_in[11];
    const float* bv1 = (const float*)d_in[12];
    const float* Wv2 = (const float*)d_in[13];
    const float* bv2 = (const float*)d_in[14];
    float* out = (float*)d_out;

    k_zero<<<(NN + 255) / 256, 256>>>();
    k_hist<<<(EE + 255) / 256, 256>>>(ei);
    k_scan<<<1, 1024>>>();
    k_fill<<<(EE + 255) / 256, 256>>>(ei);

    k_gemm1<<<dim3(D1 / 64, (NN + 63) / 64), 256>>>(X, W1);
    k_dots1<<<NN, 128>>>(as1, ad1);
    k_agg1<<<NN, 256>>>(b1);

    k_gemm2<<<dim3(HIDC / 128, (NN + 127) / 128), 256>>>(W2);
    k_dots2<<<(NN + 7) / 8, 256>>>(as2, ad2);
    k_agg2<<<NN, 256>>>(b2);

    k_pool<<<64, 256>>>();
    k_final<<<1, 128>>>(Wv1, bv1, Wv2, bv2, out);
}

// round 2
// speedup vs baseline: 2.5307x; 2.5307x over previous
#include <cuda_runtime.h>
#include <math.h>

#define NN 10000
#define EE 160000
#define FIN 70
#define HIDC 256
#define NHEADS 4
#define D1 1024   // NHEADS*HIDC

// ---------------- scratch (device globals; no allocations) ----------------
__device__ float g_h1[(size_t)NN * D1];     // layer1 pre-attention features
__device__ float g_x1[(size_t)NN * D1];     // layer1 output (relu)
__device__ float g_h2[(size_t)NN * HIDC];   // layer2 pre-attention features
__device__ float g_x2[(size_t)NN * HIDC];   // layer2 output (relu)
__device__ float g_as1[NN * NHEADS];
__device__ float g_ad1[NN * NHEADS];
__device__ float g_as2[NN];
__device__ float g_ad2[NN];
__device__ int   g_cnt[NN];
__device__ int   g_rowptr[NN + 1];
__device__ int   g_fill[NN];
__device__ int   g_csrsrc[EE];
__device__ float g_pooled[HIDC];

// ---------------- tf32 helpers ----------------
__device__ __forceinline__ float to_tf32(float x) {
    asm("cvt.rna.tf32.f32 %0, %0;" : "+f"(x));
    return x;
}

__device__ __forceinline__ void mma_tf32(float d[4], const float a[4], const float b[2]) {
    unsigned const* A = reinterpret_cast<unsigned const*>(a);
    unsigned const* B = reinterpret_cast<unsigned const*>(b);
    asm volatile(
        "mma.sync.aligned.m16n8k8.row.col.f32.tf32.tf32.f32 "
        "{%0,%1,%2,%3},{%4,%5,%6,%7},{%8,%9},{%0,%1,%2,%3};"
        : "+f"(d[0]), "+f"(d[1]), "+f"(d[2]), "+f"(d[3])
        : "r"(A[0]), "r"(A[1]), "r"(A[2]), "r"(A[3]), "r"(B[0]), "r"(B[1]));
}

// ---------------- CSR build ----------------
__global__ void k_zero() {
    int i = blockIdx.x * blockDim.x + threadIdx.x;
    if (i < NN) g_cnt[i] = 0;
    if (i < HIDC) g_pooled[i] = 0.f;
}

__global__ void k_hist(const int* __restrict__ ei) {
    int e = blockIdx.x * blockDim.x + threadIdx.x;
    if (e < EE) atomicAdd(&g_cnt[ei[EE + e]], 1);
}

__global__ void k_scan() {
    __shared__ int tile[1024];
    __shared__ int carry;
    int t = threadIdx.x;
    if (t == 0) carry = 0;
    __syncthreads();
    for (int base = 0; base < NN; base += 1024) {
        int i = base + t;
        int v = (i < NN) ? g_cnt[i] : 0;
        tile[t] = v;
        __syncthreads();
        for (int off = 1; off < 1024; off <<= 1) {
            int tmp = (t >= off) ? tile[t - off] : 0;
            __syncthreads();
            tile[t] += tmp;
            __syncthreads();
        }
        int incl = tile[t];
        int c = carry;
        if (i < NN) { g_rowptr[i] = c + incl - v; g_fill[i] = c + incl - v; }
        __syncthreads();
        if (t == 1023) carry = c + tile[1023];
        __syncthreads();
    }
    if (t == 0) g_rowptr[NN] = carry;
}

__global__ void k_fill(const int* __restrict__ ei) {
    int e = blockIdx.x * blockDim.x + threadIdx.x;
    if (e < EE) {
        int d = ei[EE + e];
        int p = atomicAdd(&g_fill[d], 1);
        g_csrsrc[p] = ei[e];
    }
}

// ---------------- GEMM1 (tf32 TC): X[N,70] @ W1[70,1024] -> g_h1 ----------------
// BM=64, BN=64, K padded 70->72. 8 warps, each 32x16 region (2m x 2n mma tiles).
#define G1_BM 64
#define G1_BN 64
#define G1_BK 72
__global__ void __launch_bounds__(256) k_gemm1_tc(const float* __restrict__ X,
                                                  const float* __restrict__ W1) {
    __shared__ float As[G1_BM][76];   // [m][k], stride 76 (conflict-free)
    __shared__ float Bs[G1_BK][72];   // [k][n], stride 72 (conflict-free)
    int m0 = blockIdx.y * G1_BM, n0 = blockIdx.x * G1_BN;
    int t = threadIdx.x;
    int warp = t >> 5, lane = t & 31;
    int g = lane >> 2, tig = lane & 3;
    int warp_m = (warp & 1) * 32;     // 2 warps along m
    int warp_n = (warp >> 1) * 16;    // 4 warps along n

    // load A tile (zero-pad k to 72, rows >= NN to 0)
    for (int idx = t; idx < G1_BM * G1_BK; idx += 256) {
        int r = idx / G1_BK, c = idx - r * G1_BK;
        int gm = m0 + r;
        float v = 0.f;
        if (c < FIN && gm < NN) v = X[(size_t)gm * FIN + c];
        As[r][c] = to_tf32(v);
    }
    // load B tile
    for (int idx = t; idx < G1_BK * G1_BN; idx += 256) {
        int k = idx >> 6, n = idx & 63;
        float v = (k < FIN) ? W1[(size_t)k * D1 + n0 + n] : 0.f;
        Bs[k][n] = to_tf32(v);
    }
    __syncthreads();

    float acc[2][2][4];
#pragma unroll
    for (int i = 0; i < 2; i++)
#pragma unroll
        for (int j = 0; j < 2; j++)
#pragma unroll
            for (int q = 0; q < 4; q++) acc[i][j][q] = 0.f;

#pragma unroll
    for (int ks = 0; ks < 9; ks++) {
        int k = ks * 8;
        float a[2][4], b[2][2];
#pragma unroll
        for (int mt = 0; mt < 2; mt++) {
            int row = warp_m + mt * 16 + g;
            a[mt][0] = As[row][k + tig];
            a[mt][1] = As[row + 8][k + tig];
            a[mt][2] = As[row][k + 4 + tig];
            a[mt][3] = As[row + 8][k + 4 + tig];
        }
#pragma unroll
        for (int nt = 0; nt < 2; nt++) {
            int col = warp_n + nt * 8 + g;
            b[nt][0] = Bs[k + tig][col];
            b[nt][1] = Bs[k + 4 + tig][col];
        }
#pragma unroll
        for (int mt = 0; mt < 2; mt++)
#pragma unroll
            for (int nt = 0; nt < 2; nt++)
                mma_tf32(acc[mt][nt], a[mt], b[nt]);
    }

#pragma unroll
    for (int mt = 0; mt < 2; mt++) {
        int r0 = m0 + warp_m + mt * 16 + g;
        int r1 = r0 + 8;
#pragma unroll
        for (int nt = 0; nt < 2; nt++) {
            int c = n0 + warp_n + nt * 8 + 2 * tig;
            if (r0 < NN) *(float2*)&g_h1[(size_t)r0 * D1 + c] = make_float2(acc[mt][nt][0], acc[mt][nt][1]);
            if (r1 < NN) *(float2*)&g_h1[(size_t)r1 * D1 + c] = make_float2(acc[mt][nt][2], acc[mt][nt][3]);
        }
    }
}

// ---------------- GEMM2 (tf32 TC): x1[N,1024] @ W2[1024,256] -> g_h2 ----------------
// BM=128, BN=128, BK=16. 8 warps: 2 along m (64 rows), 4 along n (32 cols).
__global__ void __launch_bounds__(256) k_gemm2_tc(const float* __restrict__ W2) {
    __shared__ float As[128][20];   // [m][k], stride 20 (conflict-free)
    __shared__ float Bs[16][136];   // [k][n], stride 136 (conflict-free)
    int m0 = blockIdx.y * 128, n0 = blockIdx.x * 128;
    int t = threadIdx.x;
    int warp = t >> 5, lane = t & 31;
    int g = lane >> 2, tig = lane & 3;
    int warp_m = (warp & 1) * 64;
    int warp_n = (warp >> 1) * 32;

    float acc[4][4][4];
#pragma unroll
    for (int i = 0; i < 4; i++)
#pragma unroll
        for (int j = 0; j < 4; j++)
#pragma unroll
            for (int q = 0; q < 4; q++) acc[i][j][q] = 0.f;

    int ar = t >> 1, ac = (t & 1) * 8;
    int br = t >> 5, bc4 = t & 31;

    for (int kb = 0; kb < D1; kb += 16) {
        // A tile: 128x16
        {
            int gm = m0 + ar;
            float4 v0 = make_float4(0.f, 0.f, 0.f, 0.f), v1 = v0;
            if (gm < NN) {
                v0 = *(const float4*)&g_x1[(size_t)gm * D1 + kb + ac];
                v1 = *(const float4*)&g_x1[(size_t)gm * D1 + kb + ac + 4];
            }
            v0.x = to_tf32(v0.x); v0.y = to_tf32(v0.y); v0.z = to_tf32(v0.z); v0.w = to_tf32(v0.w);
            v1.x = to_tf32(v1.x); v1.y = to_tf32(v1.y); v1.z = to_tf32(v1.z); v1.w = to_tf32(v1.w);
            *(float4*)&As[ar][ac] = v0;
            *(float4*)&As[ar][ac + 4] = v1;
        }
        // B tile: 16x128
        {
            float4 v0 = *(const float4*)&W2[(size_t)(kb + br) * HIDC + n0 + bc4 * 4];
            float4 v1 = *(const float4*)&W2[(size_t)(kb + br + 8) * HIDC + n0 + bc4 * 4];
            v0.x = to_tf32(v0.x); v0.y = to_tf32(v0.y); v0.z = to_tf32(v0.z); v0.w = to_tf32(v0.w);
            v1.x = to_tf32(v1.x); v1.y = to_tf32(v1.y); v1.z = to_tf32(v1.z); v1.w = to_tf32(v1.w);
            *(float4*)&Bs[br][bc4 * 4] = v0;
            *(float4*)&Bs[br + 8][bc4 * 4] = v1;
        }
        __syncthreads();

#pragma unroll
        for (int ks = 0; ks < 2; ks++) {
            int k = ks * 8;
            float a[4][4], b[4][2];
#pragma unroll
            for (int mt = 0; mt < 4; mt++) {
                int row = warp_m + mt * 16 + g;
                a[mt][0] = As[row][k + tig];
                a[mt][1] = As[row + 8][k + tig];
                a[mt][2] = As[row][k + 4 + tig];
                a[mt][3] = As[row + 8][k + 4 + tig];
            }
#pragma unroll
            for (int nt = 0; nt < 4; nt++) {
                int col = warp_n + nt * 8 + g;
                b[nt][0] = Bs[k + tig][col];
                b[nt][1] = Bs[k + 4 + tig][col];
            }
#pragma unroll
            for (int mt = 0; mt < 4; mt++)
#pragma unroll
                for (int nt = 0; nt < 4; nt++)
                    mma_tf32(acc[mt][nt], a[mt], b[nt]);
        }
        __syncthreads();
    }

#pragma unroll
    for (int mt = 0; mt < 4; mt++) {
        int r0 = m0 + warp_m + mt * 16 + g;
        int r1 = r0 + 8;
#pragma unroll
        for (int nt = 0; nt < 4; nt++) {
            int c = n0 + warp_n + nt * 8 + 2 * tig;
            if (r0 < NN) *(float2*)&g_h2[(size_t)r0 * HIDC + c] = make_float2(acc[mt][nt][0], acc[mt][nt][1]);
            if (r1 < NN) *(float2*)&g_h2[(size_t)r1 * HIDC + c] = make_float2(acc[mt][nt][2], acc[mt][nt][3]);
        }
    }
}

// ---------------- attention dot products ----------------
__global__ void k_dots1(const float* __restrict__ att_s, const float* __restrict__ att_d) {
    int i = blockIdx.x;
    int w = threadIdx.x >> 5, lane = threadIdx.x & 31;
    const float* hrow = g_h1 + (size_t)i * D1 + w * HIDC;
    const float* avs = att_s + w * HIDC;
    const float* avd = att_d + w * HIDC;
    float s = 0.f, d = 0.f;
    for (int c = lane; c < HIDC; c += 32) {
        float v = hrow[c];
        s += v * avs[c];
        d += v * avd[c];
    }
    for (int o = 16; o; o >>= 1) {
        s += __shfl_xor_sync(0xffffffffu, s, o);
        d += __shfl_xor_sync(0xffffffffu, d, o);
    }
    if (lane == 0) { g_as1[i * NHEADS + w] = s; g_ad1[i * NHEADS + w] = d; }
}

__global__ void k_dots2(const float* __restrict__ att_s, const float* __restrict__ att_d) {
    int w = threadIdx.x >> 5, lane = threadIdx.x & 31;
    int i = blockIdx.x * 8 + w;
    if (i >= NN) return;
    const float* hrow = g_h2 + (size_t)i * HIDC;
    float s = 0.f, d = 0.f;
    for (int c = lane; c < HIDC; c += 32) {
        float v = hrow[c];
        s += v * att_s[c];
        d += v * att_d[c];
    }
    for (int o = 16; o; o >>= 1) {
        s += __shfl_xor_sync(0xffffffffu, s, o);
        d += __shfl_xor_sync(0xffffffffu, d, o);
    }
    if (lane == 0) { g_as2[i] = s; g_ad2[i] = d; }
}

// ---------------- fused softmax + aggregation, layer 1 ----------------
__global__ void __launch_bounds__(256) k_agg1(const float* __restrict__ b1) {
    int dd = blockIdx.x, t = threadIdx.x;
    int beg = g_rowptr[dd], deg = g_rowptr[dd + 1] - beg, total = deg + 1;
    const float4* as4 = (const float4*)g_as1;
    float4 adv4 = ((const float4*)g_ad1)[dd];
    float ad[4] = {adv4.x, adv4.y, adv4.z, adv4.w};

    float mx[4] = {-1e30f, -1e30f, -1e30f, -1e30f};
    for (int j = t; j < total; j += 256) {
        int s = (j < deg) ? g_csrsrc[beg + j] : dd;
        float4 a4 = as4[s];
        float e;
        e = a4.x + ad[0]; e = e > 0.f ? e : 0.2f * e; mx[0] = fmaxf(mx[0], e);
        e = a4.y + ad[1]; e = e > 0.f ? e : 0.2f * e; mx[1] = fmaxf(mx[1], e);
        e = a4.z + ad[2]; e = e > 0.f ? e : 0.2f * e; mx[2] = fmaxf(mx[2], e);
        e = a4.w + ad[3]; e = e > 0.f ? e : 0.2f * e; mx[3] = fmaxf(mx[3], e);
    }
    __shared__ float sred[8][4];
    int lane = t & 31, w = t >> 5;
#pragma unroll
    for (int h = 0; h < 4; h++)
        for (int o = 16; o; o >>= 1) mx[h] = fmaxf(mx[h], __shfl_xor_sync(0xffffffffu, mx[h], o));
    if (lane == 0) { sred[w][0] = mx[0]; sred[w][1] = mx[1]; sred[w][2] = mx[2]; sred[w][3] = mx[3]; }
    __syncthreads();
    __shared__ float m_s[4];
    if (t < 4) {
        float m = sred[0][t];
        for (int i = 1; i < 8; i++) m = fmaxf(m, sred[i][t]);
        m_s[t] = m;
    }
    __syncthreads();
    float m[4] = {m_s[0], m_s[1], m_s[2], m_s[3]};

    __shared__ float4 sw[256];
    __shared__ int ssrc[256];
    float acc[4] = {0.f, 0.f, 0.f, 0.f};
    float dl[4] = {0.f, 0.f, 0.f, 0.f};
    for (int base = 0; base < total; base += 256) {
        int j = base + t;
        int cn = min(256, total - base);
        if (j < total) {
            int s = (j < deg) ? g_csrsrc[beg + j] : dd;
            float4 a4 = as4[s];
            float e, w0, w1, w2, w3;
            e = a4.x + ad[0]; e = e > 0.f ? e : 0.2f * e; w0 = __expf(e - m[0]); dl[0] += w0;
            e = a4.y + ad[1]; e = e > 0.f ? e : 0.2f * e; w1 = __expf(e - m[1]); dl[1] += w1;
            e = a4.z + ad[2]; e = e > 0.f ? e : 0.2f * e; w2 = __expf(e - m[2]); dl[2] += w2;
            e = a4.w + ad[3]; e = e > 0.f ? e : 0.2f * e; w3 = __expf(e - m[3]); dl[3] += w3;
            sw[t] = make_float4(w0, w1, w2, w3);
            ssrc[t] = s;
        }
        __syncthreads();
#pragma unroll 4
        for (int j2 = 0; j2 < cn; j2++) {
            int s = ssrc[j2];
            float4 wv = sw[j2];
            const float* hp = g_h1 + (size_t)s * D1 + t;
            acc[0] += wv.x * hp[0];
            acc[1] += wv.y * hp[256];
            acc[2] += wv.z * hp[512];
            acc[3] += wv.w * hp[768];
        }
        __syncthreads();
    }
#pragma unroll
    for (int h = 0; h < 4; h++)
        for (int o = 16; o; o >>= 1) dl[h] += __shfl_xor_sync(0xffffffffu, dl[h], o);
    if (lane == 0) { sred[w][0] = dl[0]; sred[w][1] = dl[1]; sred[w][2] = dl[2]; sred[w][3] = dl[3]; }
    __syncthreads();
    __shared__ float den_s[4];
    if (t < 4) {
        float s = 0.f;
        for (int i = 0; i < 8; i++) s += sred[i][t];
        den_s[t] = s;
    }
    __syncthreads();
#pragma unroll
    for (int h = 0; h < 4; h++) {
        float o = acc[h] / (den_s[h] + 1e-16f) + b1[h * HIDC + t];
        g_x1[(size_t)dd * D1 + h * HIDC + t] = o > 0.f ? o : 0.f;
    }
}

// ---------------- fused softmax + aggregation, layer 2 (1 head) ----------------
__global__ void __launch_bounds__(256) k_agg2(const float* __restrict__ b2) {
    int dd = blockIdx.x, t = threadIdx.x;
    int beg = g_rowptr[dd], deg = g_rowptr[dd + 1] - beg, total = deg + 1;
    float adv = g_ad2[dd];
    float mx = -1e30f;
    for (int j = t; j < total; j += 256) {
        int s = (j < deg) ? g_csrsrc[beg + j] : dd;
        float e = g_as2[s] + adv; e = e > 0.f ? e : 0.2f * e;
        mx = fmaxf(mx, e);
    }
    __shared__ float sred[8];
    int lane = t & 31, w = t >> 5;
    for (int o = 16; o; o >>= 1) mx = fmaxf(mx, __shfl_xor_sync(0xffffffffu, mx, o));
    if (lane == 0) sred[w] = mx;
    __syncthreads();
    __shared__ float m_s;
    if (t == 0) {
        float m = sred[0];
        for (int i = 1; i < 8; i++) m = fmaxf(m, sred[i]);
        m_s = m;
    }
    __syncthreads();
    float m = m_s;

    __shared__ float sw[256];
    __shared__ int ssrc[256];
    float acc = 0.f, dl = 0.f;
    for (int base = 0; base < total; base += 256) {
        int j = base + t;
        int cn = min(256, total - base);
        if (j < total) {
            int s = (j < deg) ? g_csrsrc[beg + j] : dd;
            float e = g_as2[s] + adv; e = e > 0.f ? e : 0.2f * e;
            float wv = __expf(e - m);
            sw[t] = wv; ssrc[t] = s; dl += wv;
        }
        __syncthreads();
#pragma unroll 4
        for (int j2 = 0; j2 < cn; j2++) {
            acc += sw[j2] * g_h2[(size_t)ssrc[j2] * HIDC + t];
        }
        __syncthreads();
    }
    for (int o = 16; o; o >>= 1) dl += __shfl_xor_sync(0xffffffffu, dl, o);
    if (lane == 0) sred[w] = dl;
    __syncthreads();
    __shared__ float den_s;
    if (t == 0) {
        float s = 0.f;
        for (int i = 0; i < 8; i++) s += sred[i];
        den_s = s;
    }
    __syncthreads();
    float o = acc / (den_s + 1e-16f) + b2[t];
    g_x2[(size_t)dd * HIDC + t] = o > 0.f ? o : 0.f;
}

// ---------------- pooling + MLP head ----------------
__global__ void k_pool() {
    int c = threadIdx.x;
    float s = 0.f;
    for (int i = blockIdx.x; i < NN; i += gridDim.x) s += g_x2[(size_t)i * HIDC + c];
    atomicAdd(&g_pooled[c], s);
}

__global__ void k_final(const float* __restrict__ Wv1, const float* __restrict__ bv1,
                        const float* __restrict__ Wv2, const float* __restrict__ bv2,
                        float* __restrict__ out) {
    __shared__ float red[128];
    int j = threadIdx.x;  // 128
    float acc = bv1[j];
    const float inv_n = 1.0f / (float)NN;
    for (int c = 0; c < HIDC; c++)
        acc += (g_pooled[c] * inv_n) * Wv1[c * 128 + j];
    float x = acc;
    float g = 0.5f * x * (1.0f + erff(x * 0.70710678118654752f));
    red[j] = g * Wv2[j];
    __syncthreads();
    for (int o = 64; o; o >>= 1) {
        if (j < o) red[j] += red[j + o];
        __syncthreads();
    }
    if (j == 0) out[0] = red[0] + bv2[0];
}

// ---------------- launch ----------------
extern "C" void kernel_launch(void* const* d_in, const int* in_sizes, int n_in,
                              void* d_out, int out_size) {
    const float* X   = (const float*)d_in[0];
    const int*   ei  = (const int*)d_in[1];
    // d_in[2] = edge_attr (ignored: GATConv has no edge_dim)
    const float* W1  = (const float*)d_in[3];
    const float* as1 = (const float*)d_in[4];
    const float* ad1 = (const float*)d_in[5];
    const float* b1  = (const float*)d_in[6];
    const float* W2  = (const float*)d_in[7];
    const float* as2 = (const float*)d_in[8];
    const float* ad2 = (const float*)d_in[9];
    const float* b2  = (const float*)d_in[10];
    const float* Wv1 = (const float*)d_in[11];
    const float* bv1 = (const float*)d_in[12];
    const float* Wv2 = (const float*)d_in[13];
    const float* bv2 = (const float*)d_in[14];
    float* out = (float*)d_out;

    k_zero<<<(NN + 255) / 256, 256>>>();
    k_hist<<<(EE + 255) / 256, 256>>>(ei);
    k_scan<<<1, 1024>>>();
    k_fill<<<(EE + 255) / 256, 256>>>(ei);

    k_gemm1_tc<<<dim3(D1 / G1_BN, (NN + G1_BM - 1) / G1_BM), 256>>>(X, W1);
    k_dots1<<<NN, 128>>>(as1, ad1);
    k_agg1<<<NN, 256>>>(b1);

    k_gemm2_tc<<<dim3(2, (NN + 127) / 128), 256>>>(W2);
    k_dots2<<<(NN + 7) / 8, 256>>>(as2, ad2);
    k_agg2<<<NN, 256>>>(b2);

    k_pool<<<64, 256>>>();
    k_final<<<1, 128>>>(Wv1, bv1, Wv2, bv2, out);
}

// round 5
// speedup vs baseline: 2.8635x; 1.1315x over previous
#include <cuda_runtime.h>
#include <cuda_bf16.h>
#include <math.h>

#define NN 10000
#define EE 160000
#define FIN 70
#define HIDC 256
#define NHEADS 4
#define D1 1024   // NHEADS*HIDC

// ---------------- scratch (device globals; no allocations) ----------------
__device__ __nv_bfloat16 g_h1b[(size_t)NN * D1];   // layer1 pre-attention features (bf16)
__device__ __nv_bfloat16 g_x1b[(size_t)NN * D1];   // layer1 output relu (bf16)
__device__ __nv_bfloat16 g_h2b[(size_t)NN * HIDC]; // layer2 pre-attention features (bf16)
__device__ __nv_bfloat16 g_w2bT[(size_t)HIDC * D1];// W2 transposed bf16: [n][k]
__device__ float g_as1[NN * NHEADS];
__device__ float g_ad1[NN * NHEADS];
__device__ float g_as2[NN];
__device__ float g_ad2[NN];
__device__ int   g_cnt[NN];
__device__ int   g_rowptr[NN + 1];
__device__ int   g_fill[NN];
__device__ int   g_csrsrc[EE];
__device__ float g_pooled[HIDC];

// ---------------- mma helpers ----------------
__device__ __forceinline__ float to_tf32(float x) {
    asm("cvt.rna.tf32.f32 %0, %0;" : "+f"(x));
    return x;
}

__device__ __forceinline__ void mma_tf32(float d[4], const float a[4], const float b[2]) {
    unsigned const* A = reinterpret_cast<unsigned const*>(a);
    unsigned const* B = reinterpret_cast<unsigned const*>(b);
    asm volatile(
        "mma.sync.aligned.m16n8k8.row.col.f32.tf32.tf32.f32 "
        "{%0,%1,%2,%3},{%4,%5,%6,%7},{%8,%9},{%0,%1,%2,%3};"
        : "+f"(d[0]), "+f"(d[1]), "+f"(d[2]), "+f"(d[3])
        : "r"(A[0]), "r"(A[1]), "r"(A[2]), "r"(A[3]), "r"(B[0]), "r"(B[1]));
}

__device__ __forceinline__ void mma_bf16(float d[4], const unsigned a[4], const unsigned b[2]) {
    asm volatile(
        "mma.sync.aligned.m16n8k16.row.col.f32.bf16.bf16.f32 "
        "{%0,%1,%2,%3},{%4,%5,%6,%7},{%8,%9},{%0,%1,%2,%3};"
        : "+f"(d[0]), "+f"(d[1]), "+f"(d[2]), "+f"(d[3])
        : "r"(a[0]), "r"(a[1]), "r"(a[2]), "r"(a[3]), "r"(b[0]), "r"(b[1]));
}

// ---------------- CSR build ----------------
__global__ void k_zero() {
    int i = blockIdx.x * blockDim.x + threadIdx.x;
    if (i < NN) { g_cnt[i] = 0; g_as2[i] = 0.f; g_ad2[i] = 0.f; }
    if (i < NN * NHEADS) { g_as1[i] = 0.f; g_ad1[i] = 0.f; }
    if (i < HIDC) g_pooled[i] = 0.f;
}

__global__ void k_hist(const int* __restrict__ ei) {
    int e = blockIdx.x * blockDim.x + threadIdx.x;
    if (e < EE) atomicAdd(&g_cnt[ei[EE + e]], 1);
}

__global__ void k_scan() {
    __shared__ int wsum[32];
    __shared__ int carry;
    int t = threadIdx.x, lane = t & 31, w = t >> 5;
    if (t == 0) carry = 0;
    __syncthreads();
    for (int base = 0; base < NN; base += 1024) {
        int i = base + t;
        int v = (i < NN) ? g_cnt[i] : 0;
        int x = v;
#pragma unroll
        for (int o = 1; o < 32; o <<= 1) {
            int y = __shfl_up_sync(0xffffffffu, x, o);
            if (lane >= o) x += y;
        }
        if (lane == 31) wsum[w] = x;
        __syncthreads();
        if (w == 0) {
            int s = wsum[lane];
#pragma unroll
            for (int o = 1; o < 32; o <<= 1) {
                int y = __shfl_up_sync(0xffffffffu, s, o);
                if (lane >= o) s += y;
            }
            wsum[lane] = s;
        }
        __syncthreads();
        int excl = x - v + (w ? wsum[w - 1] : 0) + carry;
        if (i < NN) { g_rowptr[i] = excl; g_fill[i] = excl; }
        __syncthreads();
        if (t == 1023) carry = excl + v;
        __syncthreads();
    }
    if (t == 0) g_rowptr[NN] = carry;
}

__global__ void k_fill(const int* __restrict__ ei) {
    int e = blockIdx.x * blockDim.x + threadIdx.x;
    if (e < EE) {
        int d = ei[EE + e];
        int p = atomicAdd(&g_fill[d], 1);
        g_csrsrc[p] = ei[e];
    }
}

// ---------------- W2 -> bf16 transposed ----------------
__global__ void k_w2conv(const float* __restrict__ W2) {
    int idx = blockIdx.x * blockDim.x + threadIdx.x;   // D1*HIDC
    int k = idx >> 8, n = idx & 255;
    g_w2bT[(size_t)n * D1 + k] = __float2bfloat16(W2[idx]);
}

// ---------------- GEMM1 (tf32 TC) + fused dots1 + bf16 store ----------------
#define G1_BM 64
#define G1_BN 64
#define G1_BK 72
__global__ void __launch_bounds__(256) k_gemm1_tc(const float* __restrict__ X,
                                                  const float* __restrict__ W1,
                                                  const float* __restrict__ att_s,
                                                  const float* __restrict__ att_d) {
    __shared__ float As[G1_BM][76];
    __shared__ float Bs[G1_BK][72];
    int m0 = blockIdx.y * G1_BM, n0 = blockIdx.x * G1_BN;
    int t = threadIdx.x;
    int warp = t >> 5, lane = t & 31;
    int g = lane >> 2, tig = lane & 3;
    int warp_m = (warp & 1) * 32;
    int warp_n = (warp >> 1) * 16;

    for (int idx = t; idx < G1_BM * G1_BK; idx += 256) {
        int r = idx / G1_BK, c = idx - r * G1_BK;
        int gm = m0 + r;
        float v = 0.f;
        if (c < FIN && gm < NN) v = X[(size_t)gm * FIN + c];
        As[r][c] = to_tf32(v);
    }
    for (int idx = t; idx < G1_BK * G1_BN; idx += 256) {
        int k = idx >> 6, n = idx & 63;
        float v = (k < FIN) ? W1[(size_t)k * D1 + n0 + n] : 0.f;
        Bs[k][n] = to_tf32(v);
    }
    __syncthreads();

    float acc[2][2][4];
#pragma unroll
    for (int i = 0; i < 2; i++)
#pragma unroll
        for (int j = 0; j < 2; j++)
#pragma unroll
            for (int q = 0; q < 4; q++) acc[i][j][q] = 0.f;

#pragma unroll
    for (int ks = 0; ks < 9; ks++) {
        int k = ks * 8;
        float a[2][4], b[2][2];
#pragma unroll
        for (int mt = 0; mt < 2; mt++) {
            int row = warp_m + mt * 16 + g;
            a[mt][0] = As[row][k + tig];
            a[mt][1] = As[row + 8][k + tig];
            a[mt][2] = As[row][k + 4 + tig];
            a[mt][3] = As[row + 8][k + 4 + tig];
        }
#pragma unroll
        for (int nt = 0; nt < 2; nt++) {
            int col = warp_n + nt * 8 + g;
            b[nt][0] = Bs[k + tig][col];
            b[nt][1] = Bs[k + 4 + tig][col];
        }
#pragma unroll
        for (int mt = 0; mt < 2; mt++)
#pragma unroll
            for (int nt = 0; nt < 2; nt++)
                mma_tf32(acc[mt][nt], a[mt], b[nt]);
    }

    // fused dots1 partials + bf16 feature store
    __shared__ float sAs[G1_BM], sAd[G1_BM];
    if (t < G1_BM) { sAs[t] = 0.f; sAd[t] = 0.f; }
    __syncthreads();
    int h = n0 >> 8;
    const float* avs = att_s + h * HIDC + (n0 & 255);
    const float* avd = att_d + h * HIDC + (n0 & 255);
#pragma unroll
    for (int mt = 0; mt < 2; mt++) {
        float ps0 = 0.f, pd0 = 0.f, ps1 = 0.f, pd1 = 0.f;
#pragma unroll
        for (int nt = 0; nt < 2; nt++) {
            int c = warp_n + nt * 8 + 2 * tig;
            float s0 = avs[c], s1 = avs[c + 1], dv0 = avd[c], dv1 = avd[c + 1];
            ps0 += acc[mt][nt][0] * s0 + acc[mt][nt][1] * s1;
            pd0 += acc[mt][nt][0] * dv0 + acc[mt][nt][1] * dv1;
            ps1 += acc[mt][nt][2] * s0 + acc[mt][nt][3] * s1;
            pd1 += acc[mt][nt][2] * dv0 + acc[mt][nt][3] * dv1;
        }
        int lr0 = warp_m + mt * 16 + g, lr1 = lr0 + 8;
        atomicAdd(&sAs[lr0], ps0); atomicAdd(&sAd[lr0], pd0);
        atomicAdd(&sAs[lr1], ps1); atomicAdd(&sAd[lr1], pd1);
        int r0 = m0 + lr0, r1 = m0 + lr1;
#pragma unroll
        for (int nt = 0; nt < 2; nt++) {
            int c = n0 + warp_n + nt * 8 + 2 * tig;
            if (r0 < NN) *(__nv_bfloat162*)&g_h1b[(size_t)r0 * D1 + c] =
                __floats2bfloat162_rn(acc[mt][nt][0], acc[mt][nt][1]);
            if (r1 < NN) *(__nv_bfloat162*)&g_h1b[(size_t)r1 * D1 + c] =
                __floats2bfloat162_rn(acc[mt][nt][2], acc[mt][nt][3]);
        }
    }
    __syncthreads();
    if (t < G1_BM && m0 + t < NN) {
        atomicAdd(&g_as1[(m0 + t) * NHEADS + h], sAs[t]);
        atomicAdd(&g_ad1[(m0 + t) * NHEADS + h], sAd[t]);
    }
}

// ---------------- GEMM2 (bf16 TC) + fused dots2 + bf16 store ----------------
__global__ void __launch_bounds__(256) k_gemm2_bf(const float* __restrict__ att_s,
                                                  const float* __restrict__ att_d) {
    __shared__ __nv_bfloat16 As2[128][40];
    __shared__ __nv_bfloat16 Bs2[128][40];
    int m0 = blockIdx.y * 128, n0 = blockIdx.x * 128;
    int t = threadIdx.x;
    int warp = t >> 5, lane = t & 31;
    int g = lane >> 2, tig = lane & 3;
    int warp_m = (warp & 1) * 64;
    int warp_n = (warp >> 1) * 32;

    float acc[4][4][4];
#pragma unroll
    for (int i = 0; i < 4; i++)
#pragma unroll
        for (int j = 0; j < 4; j++)
#pragma unroll
            for (int q = 0; q < 4; q++) acc[i][j][q] = 0.f;

    int ar = t >> 1, ak = (t & 1) * 16;   // each thread fills 16 bf16 = two uint4

    for (int kb = 0; kb < D1; kb += 32) {
        {
            int gm = m0 + ar;
            uint4 v0 = make_uint4(0u, 0u, 0u, 0u), v1 = v0;
            if (gm < NN) {
                v0 = *(const uint4*)&g_x1b[(size_t)gm * D1 + kb + ak];
                v1 = *(const uint4*)&g_x1b[(size_t)gm * D1 + kb + ak + 8];
            }
            *(uint4*)&As2[ar][ak] = v0;
            *(uint4*)&As2[ar][ak + 8] = v1;
            uint4 w0 = *(const uint4*)&g_w2bT[(size_t)(n0 + ar) * D1 + kb + ak];
            uint4 w1 = *(const uint4*)&g_w2bT[(size_t)(n0 + ar) * D1 + kb + ak + 8];
            *(uint4*)&Bs2[ar][ak] = w0;
            *(uint4*)&Bs2[ar][ak + 8] = w1;
        }
        __syncthreads();
#pragma unroll
        for (int ks = 0; ks < 2; ks++) {
            int kk = ks * 16;
            unsigned a[4][4], b[4][2];
#pragma unroll
            for (int mt = 0; mt < 4; mt++) {
                int row = warp_m + mt * 16 + g;
                a[mt][0] = *(const unsigned*)&As2[row][kk + 2 * tig];
                a[mt][1] = *(const unsigned*)&As2[row + 8][kk + 2 * tig];
                a[mt][2] = *(const unsigned*)&As2[row][kk + 8 + 2 * tig];
                a[mt][3] = *(const unsigned*)&As2[row + 8][kk + 8 + 2 * tig];
            }
#pragma unroll
            for (int nt = 0; nt < 4; nt++) {
                int col = warp_n + nt * 8 + g;
                b[nt][0] = *(const unsigned*)&Bs2[col][kk + 2 * tig];
                b[nt][1] = *(const unsigned*)&Bs2[col][kk + 8 + 2 * tig];
            }
#pragma unroll
            for (int mt = 0; mt < 4; mt++)
#pragma unroll
                for (int nt = 0; nt < 4; nt++)
                    mma_bf16(acc[mt][nt], a[mt], b[nt]);
        }
        __syncthreads();
    }

    // fused dots2 partials + bf16 feature store
    __shared__ float sAs[128], sAd[128];
    if (t < 128) { sAs[t] = 0.f; sAd[t] = 0.f; }
    __syncthreads();
    const float* avs = att_s + n0;
    const float* avd = att_d + n0;
#pragma unroll
    for (int mt = 0; mt < 4; mt++) {
        float ps0 = 0.f, pd0 = 0.f, ps1 = 0.f, pd1 = 0.f;
#pragma unroll
        for (int nt = 0; nt < 4; nt++) {
            int c = warp_n + nt * 8 + 2 * tig;
            float s0 = avs[c], s1 = avs[c + 1], dv0 = avd[c], dv1 = avd[c + 1];
            ps0 += acc[mt][nt][0] * s0 + acc[mt][nt][1] * s1;
            pd0 += acc[mt][nt][0] * dv0 + acc[mt][nt][1] * dv1;
            ps1 += acc[mt][nt][2] * s0 + acc[mt][nt][3] * s1;
            pd1 += acc[mt][nt][2] * dv0 + acc[mt][nt][3] * dv1;
        }
        int lr0 = warp_m + mt * 16 + g, lr1 = lr0 + 8;
        atomicAdd(&sAs[lr0], ps0); atomicAdd(&sAd[lr0], pd0);
        atomicAdd(&sAs[lr1], ps1); atomicAdd(&sAd[lr1], pd1);
        int r0 = m0 + lr0, r1 = m0 + lr1;
#pragma unroll
        for (int nt = 0; nt < 4; nt++) {
            int c = n0 + warp_n + nt * 8 + 2 * tig;
            if (r0 < NN) *(__nv_bfloat162*)&g_h2b[(size_t)r0 * HIDC + c] =
                __floats2bfloat162_rn(acc[mt][nt][0], acc[mt][nt][1]);
            if (r1 < NN) *(__nv_bfloat162*)&g_h2b[(size_t)r1 * HIDC + c] =
                __floats2bfloat162_rn(acc[mt][nt][2], acc[mt][nt][3]);
        }
    }
    __syncthreads();
    if (t < 128 && m0 + t < NN) {
        atomicAdd(&g_as2[m0 + t], sAs[t]);
        atomicAdd(&g_ad2[m0 + t], sAd[t]);
    }
}

// ---------------- fused softmax + aggregation, layer 1 ----------------
__global__ void __launch_bounds__(256) k_agg1(const float* __restrict__ b1) {
    int dd = blockIdx.x, t = threadIdx.x;
    int beg = g_rowptr[dd], deg = g_rowptr[dd + 1] - beg, total = deg + 1;
    const float4* as4 = (const float4*)g_as1;
    float4 adv4 = ((const float4*)g_ad1)[dd];
    float ad[4] = {adv4.x, adv4.y, adv4.z, adv4.w};

    float mx[4] = {-1e30f, -1e30f, -1e30f, -1e30f};
    for (int j = t; j < total; j += 256) {
        int s = (j < deg) ? g_csrsrc[beg + j] : dd;
        float4 a4 = as4[s];
        float e;
        e = a4.x + ad[0]; e = e > 0.f ? e : 0.2f * e; mx[0] = fmaxf(mx[0], e);
        e = a4.y + ad[1]; e = e > 0.f ? e : 0.2f * e; mx[1] = fmaxf(mx[1], e);
        e = a4.z + ad[2]; e = e > 0.f ? e : 0.2f * e; mx[2] = fmaxf(mx[2], e);
        e = a4.w + ad[3]; e = e > 0.f ? e : 0.2f * e; mx[3] = fmaxf(mx[3], e);
    }
    __shared__ float sred[8][4];
    int lane = t & 31, w = t >> 5;
#pragma unroll
    for (int h = 0; h < 4; h++)
        for (int o = 16; o; o >>= 1) mx[h] = fmaxf(mx[h], __shfl_xor_sync(0xffffffffu, mx[h], o));
    if (lane == 0) { sred[w][0] = mx[0]; sred[w][1] = mx[1]; sred[w][2] = mx[2]; sred[w][3] = mx[3]; }
    __syncthreads();
    __shared__ float m_s[4];
    if (t < 4) {
        float m = sred[0][t];
        for (int i = 1; i < 8; i++) m = fmaxf(m, sred[i][t]);
        m_s[t] = m;
    }
    __syncthreads();
    float m[4] = {m_s[0], m_s[1], m_s[2], m_s[3]};

    __shared__ float4 sw[256];
    __shared__ int ssrc[256];
    float acc[4] = {0.f, 0.f, 0.f, 0.f};
    float dl[4] = {0.f, 0.f, 0.f, 0.f};
    for (int base = 0; base < total; base += 256) {
        int j = base + t;
        int cn = min(256, total - base);
        if (j < total) {
            int s = (j < deg) ? g_csrsrc[beg + j] : dd;
            float4 a4 = as4[s];
            float e, w0, w1, w2, w3;
            e = a4.x + ad[0]; e = e > 0.f ? e : 0.2f * e; w0 = __expf(e - m[0]); dl[0] += w0;
            e = a4.y + ad[1]; e = e > 0.f ? e : 0.2f * e; w1 = __expf(e - m[1]); dl[1] += w1;
            e = a4.z + ad[2]; e = e > 0.f ? e : 0.2f * e; w2 = __expf(e - m[2]); dl[2] += w2;
            e = a4.w + ad[3]; e = e > 0.f ? e : 0.2f * e; w3 = __expf(e - m[3]); dl[3] += w3;
            sw[t] = make_float4(w0, w1, w2, w3);
            ssrc[t] = s;
        }
        __syncthreads();
#pragma unroll 4
        for (int j2 = 0; j2 < cn; j2++) {
            int s = ssrc[j2];
            float4 wv = sw[j2];
            const __nv_bfloat16* hp = g_h1b + (size_t)s * D1 + t;
            acc[0] += wv.x * __bfloat162float(hp[0]);
            acc[1] += wv.y * __bfloat162float(hp[256]);
            acc[2] += wv.z * __bfloat162float(hp[512]);
            acc[3] += wv.w * __bfloat162float(hp[768]);
        }
        __syncthreads();
    }
#pragma unroll
    for (int h = 0; h < 4; h++)
        for (int o = 16; o; o >>= 1) dl[h] += __shfl_xor_sync(0xffffffffu, dl[h], o);
    if (lane == 0) { sred[w][0] = dl[0]; sred[w][1] = dl[1]; sred[w][2] = dl[2]; sred[w][3] = dl[3]; }
    __syncthreads();
    __shared__ float den_s[4];
    if (t < 4) {
        float s = 0.f;
        for (int i = 0; i < 8; i++) s += sred[i][t];
        den_s[t] = s;
    }
    __syncthreads();
#pragma unroll
    for (int h = 0; h < 4; h++) {
        float o = acc[h] / (den_s[h] + 1e-16f) + b1[h * HIDC + t];
        g_x1b[(size_t)dd * D1 + h * HIDC + t] = __float2bfloat16(o > 0.f ? o : 0.f);
    }
}

// ---------------- fused softmax + aggregation + pooling, layer 2 ----------------
__global__ void __launch_bounds__(256) k_agg2(const float* __restrict__ b2) {
    int dd = blockIdx.x, t = threadIdx.x;
    int beg = g_rowptr[dd], deg = g_rowptr[dd + 1] - beg, total = deg + 1;
    float adv = g_ad2[dd];
    float mx = -1e30f;
    for (int j = t; j < total; j += 256) {
        int s = (j < deg) ? g_csrsrc[beg + j] : dd;
        float e = g_as2[s] + adv; e = e > 0.f ? e : 0.2f * e;
        mx = fmaxf(mx, e);
    }
    __shared__ float sred[8];
    int lane = t & 31, w = t >> 5;
    for (int o = 16; o; o >>= 1) mx = fmaxf(mx, __shfl_xor_sync(0xffffffffu, mx, o));
    if (lane == 0) sred[w] = mx;
    __syncthreads();
    __shared__ float m_s;
    if (t == 0) {
        float m = sred[0];
        for (int i = 1; i < 8; i++) m = fmaxf(m, sred[i]);
        m_s = m;
    }
    __syncthreads();
    float m = m_s;

    __shared__ float sw[256];
    __shared__ int ssrc[256];
    float acc = 0.f, dl = 0.f;
    for (int base = 0; base < total; base += 256) {
        int j = base + t;
        int cn = min(256, total - base);
        if (j < total) {
            int s = (j < deg) ? g_csrsrc[beg + j] : dd;
            float e = g_as2[s] + adv; e = e > 0.f ? e : 0.2f * e;
            float wv = __expf(e - m);
            sw[t] = wv; ssrc[t] = s; dl += wv;
        }
        __syncthreads();
#pragma unroll 4
        for (int j2 = 0; j2 < cn; j2++) {
            acc += sw[j2] * __bfloat162float(g_h2b[(size_t)ssrc[j2] * HIDC + t]);
        }
        __syncthreads();
    }
    for (int o = 16; o; o >>= 1) dl += __shfl_xor_sync(0xffffffffu, dl, o);
    if (lane == 0) sred[w] = dl;
    __syncthreads();
    __shared__ float den_s;
    if (t == 0) {
        float s = 0.f;
        for (int i = 0; i < 8; i++) s += sred[i];
        den_s = s;
    }
    __syncthreads();
    float o = acc / (den_s + 1e-16f) + b2[t];
    o = o > 0.f ? o : 0.f;
    atomicAdd(&g_pooled[t], o);
}

// ---------------- MLP head ----------------
__global__ void k_final(const float* __restrict__ Wv1, const float* __restrict__ bv1,
                        const float* __restrict__ Wv2, const float* __restrict__ bv2,
                        float* __restrict__ out) {
    __shared__ float red[128];
    int j = threadIdx.x;  // 128
    float acc = bv1[j];
    const float inv_n = 1.0f / (float)NN;
    for (int c = 0; c < HIDC; c++)
        acc += (g_pooled[c] * inv_n) * Wv1[c * 128 + j];
    float x = acc;
    float g = 0.5f * x * (1.0f + erff(x * 0.70710678118654752f));
    red[j] = g * Wv2[j];
    __syncthreads();
    for (int o = 64; o; o >>= 1) {
        if (j < o) red[j] += red[j + o];
        __syncthreads();
    }
    if (j == 0) out[0] = red[0] + bv2[0];
}

// ---------------- launch ----------------
extern "C" void kernel_launch(void* const* d_in, const int* in_sizes, int n_in,
                              void* d_out, int out_size) {
    const float* X   = (const float*)d_in[0];
    const int*   ei  = (const int*)d_in[1];
    // d_in[2] = edge_attr (ignored: GATConv has no edge_dim)
    const float* W1  = (const float*)d_in[3];
    const float* as1 = (const float*)d_in[4];
    const float* ad1 = (const float*)d_in[5];
    const float* b1  = (const float*)d_in[6];
    const float* W2  = (const float*)d_in[7];
    const float* as2 = (const float*)d_in[8];
    const float* ad2 = (const float*)d_in[9];
    const float* b2  = (const float*)d_in[10];
    const float* Wv1 = (const float*)d_in[11];
    const float* bv1 = (const float*)d_in[12];
    const float* Wv2 = (const float*)d_in[13];
    const float* bv2 = (const float*)d_in[14];
    float* out = (float*)d_out;

    k_zero<<<(NN * NHEADS + 255) / 256, 256>>>();
    k_hist<<<(EE + 255) / 256, 256>>>(ei);
    k_scan<<<1, 1024>>>();
    k_fill<<<(EE + 255) / 256, 256>>>(ei);
    k_w2conv<<<(D1 * HIDC) / 256, 256>>>(W2);

    k_gemm1_tc<<<dim3(D1 / G1_BN, (NN + G1_BM - 1) / G1_BM), 256>>>(X, W1, as1, ad1);
    k_agg1<<<NN, 256>>>(b1);

    k_gemm2_bf<<<dim3(2, (NN + 127) / 128), 256>>>(as2, ad2);
    k_agg2<<<NN, 256>>>(b2);

    k_final<<<1, 128>>>(Wv1, bv1, Wv2, bv2, out);
}